// round 16
// baseline (speedup 1.0000x reference)
#include <cuda_runtime.h>

#define DD   256
#define E2   512
#define NT   128
#define NF   128
#define NBN  16
#define SROW 516
#define EPS  1e-5f

typedef unsigned long long u64;

// ---------------- packed f32x2 helpers (Blackwell 2xFP32) ------------------
__device__ __forceinline__ u64 add2(u64 a, u64 b) {
    u64 d; asm("add.rn.f32x2 %0,%1,%2;" : "=l"(d) : "l"(a), "l"(b)); return d;
}
__device__ __forceinline__ u64 fma2(u64 a, u64 b, u64 c) {
    u64 d; asm("fma.rn.f32x2 %0,%1,%2,%3;" : "=l"(d) : "l"(a), "l"(b), "l"(c)); return d;
}
__device__ __forceinline__ u64 relu2(u64 a) {
    u64 d;
    asm("{\n\t.reg .f32 l,h;\n\tmov.b64 {l,h}, %1;\n\t"
        "max.f32 l, l, 0f00000000;\n\tmax.f32 h, h, 0f00000000;\n\t"
        "mov.b64 %0, {l,h};\n\t}" : "=l"(d) : "l"(a));
    return d;
}
__device__ __forceinline__ float sum2(u64 a) {
    float l, h; asm("mov.b64 {%0,%1}, %2;" : "=f"(l), "=f"(h) : "l"(a)); return l + h;
}
__device__ __forceinline__ u64 pack2(float v) {
    u64 d; asm("mov.b64 %0, {%1,%1};" : "=l"(d) : "f"(v)); return d;
}

// ---------------- scratch (device globals; no allocation allowed) ----------
__device__ float g_qx[NBN];
__device__ float g_qt[NT];
__device__ float g_qf[NF];
__device__ float g_dxt[NBN * NT];
__device__ float g_dxf[NBN * NF];
__device__ float g_dtf[NT * NF];
// two projection half-k buffers: every slot plain-stored exactly once per
// buffer (no memset, no atomics). k_main adds A+B during fill.
#define U_TOTAL ((NBN + NT + NF) * E2 + E2)
__device__ __align__(16) float g_uA[U_TOTAL];
__device__ __align__(16) float g_uB[U_TOTAL];
#define OFF_UT (NBN * E2)
#define OFF_UF ((NBN + NT) * E2)
#define OFF_C  ((NBN + NT + NF) * E2)

// row id r in [0,272): 0..15 x, 16..143 t_emb, 144..271 f_emb
__device__ __forceinline__ const float* row_ptr(int r, const float* x,
                                                const float* t_emb,
                                                const float* f_emb) {
    if (r < 16)  return x + r * DD;
    if (r < 144) return t_emb + (r - 16) * DD;
    return f_emb + (r - 144) * DD;
}

// ---------------- P1 (single prep kernel) ----------------------------------
// blocks [0, 70):        W1 projection, 8 rows x half-k each (long pole, first)
// blocks [70, 86):       dtf GEMM tiles: 8 t-rows x 128 f per block
// blocks [86, 86+273):   dxt/dxf/q dots, 16 warps/block, one result per warp
#define PROJ_GROUPS 35
#define PROJ_BLOCKS (PROJ_GROUPS * 2)
#define PROJ_ROWS   8
#define PROJ_K      128
#define DTF_BLOCKS  16
#define DOTB_FIRST  (PROJ_BLOCKS + DTF_BLOCKS)          // 86
#define DOTB_COUNT  273                                 // ceil(4368/16)
__global__ void __launch_bounds__(512)
k_prep(const float* __restrict__ x,
       const float* __restrict__ t_emb,
       const float* __restrict__ f_emb,
       const float* __restrict__ ln_g,
       const float* __restrict__ ln_b,
       const float* __restrict__ W1,
       const float* __restrict__ b1) {
    int tid  = threadIdx.x;
    int lane = tid & 31;
    int wid  = tid >> 5;

    if (blockIdx.x >= DOTB_FIRST) {
        // ------------- dxt / dxf / q segment (4368 warps) -------------
        int w = (blockIdx.x - DOTB_FIRST) * 16 + wid;
        if (w >= 4368) return;
        int ra, rb;
        float* dst;
        if (w < 2048) {                        // dxt: x . t
            ra = w >> 7; rb = 16 + (w & 127); dst = g_dxt + w;
        } else if (w < 4096) {                 // dxf: x . f
            int w2 = w - 2048;
            ra = w2 >> 7; rb = 144 + (w2 & 127); dst = g_dxf + w2;
        } else {                               // self q
            int r = w - 4096;                  // 0..271
            const float4* a4 = (const float4*)row_ptr(r, x, t_emb, f_emb);
            float4 a0 = a4[lane * 2], a1 = a4[lane * 2 + 1];
            float sa  = a0.x + a0.y + a0.z + a0.w + a1.x + a1.y + a1.z + a1.w;
            float saa = a0.x * a0.x + a0.y * a0.y + a0.z * a0.z + a0.w * a0.w
                      + a1.x * a1.x + a1.y * a1.y + a1.z * a1.z + a1.w * a1.w;
            #pragma unroll
            for (int o = 16; o; o >>= 1) {
                sa  += __shfl_xor_sync(0xffffffffu, sa, o);
                saa += __shfl_xor_sync(0xffffffffu, saa, o);
            }
            if (lane == 0) {
                float q = saa - sa * sa * (1.0f / DD);
                if (r < 16)       g_qx[r] = q;
                else if (r < 144) g_qt[r - 16] = q;
                else              g_qf[r - 144] = q;
            }
            return;
        }
        const float4* a4 = (const float4*)row_ptr(ra, x, t_emb, f_emb);
        const float4* b4 = (const float4*)row_ptr(rb, x, t_emb, f_emb);
        float4 a0 = a4[lane * 2], a1 = a4[lane * 2 + 1];
        float4 b0 = b4[lane * 2], b1v = b4[lane * 2 + 1];
        float sa  = a0.x + a0.y + a0.z + a0.w + a1.x + a1.y + a1.z + a1.w;
        float sb  = b0.x + b0.y + b0.z + b0.w + b1v.x + b1v.y + b1v.z + b1v.w;
        float sab = a0.x * b0.x + a0.y * b0.y + a0.z * b0.z + a0.w * b0.w
                  + a1.x * b1v.x + a1.y * b1v.y + a1.z * b1v.z + a1.w * b1v.w;
        #pragma unroll
        for (int o = 16; o; o >>= 1) {
            sa  += __shfl_xor_sync(0xffffffffu, sa, o);
            sb  += __shfl_xor_sync(0xffffffffu, sb, o);
            sab += __shfl_xor_sync(0xffffffffu, sab, o);
        }
        if (lane == 0) *dst = sab - sa * sb * (1.0f / DD);
        return;
    }

    if (blockIdx.x >= PROJ_BLOCKS) {
        // ------------- dtf GEMM tile: 8 t-rows x all 128 f -------------
        __shared__ float st[8][DD];
        __shared__ float ssum[8];
        int t0 = (blockIdx.x - PROJ_BLOCKS) * 8;

        for (int i = tid; i < 8 * DD; i += 512)
            st[i >> 8][i & 255] = t_emb[t0 * DD + i];
        __syncthreads();

        if (wid < 8) {   // row sums
            const float4* r4 = (const float4*)st[wid];
            float4 v0 = r4[lane * 2], v1 = r4[lane * 2 + 1];
            float s = v0.x + v0.y + v0.z + v0.w + v1.x + v1.y + v1.z + v1.w;
            #pragma unroll
            for (int o = 16; o; o >>= 1) s += __shfl_xor_sync(0xffffffffu, s, o);
            if (lane == 0) ssum[wid] = s;
        }
        __syncthreads();

        // warp wid handles f rows [wid*8, wid*8+8)
        for (int fi = 0; fi < 8; fi++) {
            int f = wid * 8 + fi;
            const float4* f4 = (const float4*)(f_emb + f * DD);
            float4 a0 = f4[lane * 2], a1 = f4[lane * 2 + 1];
            float sf = a0.x + a0.y + a0.z + a0.w + a1.x + a1.y + a1.z + a1.w;
            float acc[8];
            #pragma unroll
            for (int tl = 0; tl < 8; tl++) {
                const float4* s4 = (const float4*)st[tl];
                float4 b0 = s4[lane * 2], b1v = s4[lane * 2 + 1];
                acc[tl] = a0.x * b0.x + a0.y * b0.y + a0.z * b0.z + a0.w * b0.w
                        + a1.x * b1v.x + a1.y * b1v.y + a1.z * b1v.z + a1.w * b1v.w;
            }
            #pragma unroll
            for (int o = 16; o; o >>= 1) {
                sf += __shfl_xor_sync(0xffffffffu, sf, o);
                #pragma unroll
                for (int tl = 0; tl < 8; tl++)
                    acc[tl] += __shfl_xor_sync(0xffffffffu, acc[tl], o);
            }
            if (lane == 0) {
                #pragma unroll
                for (int tl = 0; tl < 8; tl++)
                    g_dtf[(t0 + tl) * NF + f] = acc[tl] - ssum[tl] * sf * (1.0f / DD);
            }
        }
        return;
    }

    // ---------------- projection segment (k-split halves, plain stores) ----
    __shared__ float  s_mu[PROJ_ROWS];
    __shared__ float4 cgA[PROJ_K];   // [kk] -> rows r0..r0+3
    __shared__ float4 cgB[PROJ_K];   // [kk] -> rows r0+4..r0+7
    int half = blockIdx.x & 1;
    int rg   = blockIdx.x >> 1;
    int r0   = rg * PROJ_ROWS;
    int k0   = half * PROJ_K;
    float* ubuf = half ? g_uB : g_uA;

    if (wid < PROJ_ROWS) {
        int r = r0 + wid;
        float mu = 0.f;
        if (r < 272) {
            const float4* a4 = (const float4*)row_ptr(r, x, t_emb, f_emb);
            float4 a0 = a4[lane * 2], a1 = a4[lane * 2 + 1];
            float s = a0.x + a0.y + a0.z + a0.w + a1.x + a1.y + a1.z + a1.w;
            #pragma unroll
            for (int o = 16; o; o >>= 1) s += __shfl_xor_sync(0xffffffffu, s, o);
            mu = s * (1.0f / DD);
        }
        if (lane == 0) s_mu[wid] = mu;
    }
    __syncthreads();

    if (tid < PROJ_K) {
        int k = k0 + tid;
        float g = ln_g[k];
        float v[PROJ_ROWS];
        #pragma unroll
        for (int j = 0; j < PROJ_ROWS; j++) {
            int r = r0 + j;
            float c;
            if (r < 272)       c = (row_ptr(r, x, t_emb, f_emb)[k] - s_mu[j]) * g;
            else if (r == 272) c = ln_b[k];
            else               c = 0.f;
            v[j] = c;
        }
        cgA[tid] = make_float4(v[0], v[1], v[2], v[3]);
        cgB[tid] = make_float4(v[4], v[5], v[6], v[7]);
    }
    __syncthreads();

    int e = tid;                 // 0..511
    float acc[PROJ_ROWS];
    #pragma unroll
    for (int j = 0; j < PROJ_ROWS; j++) acc[j] = 0.f;
    #pragma unroll 16
    for (int kk = 0; kk < PROJ_K; kk++) {
        float w = W1[(k0 + kk) * E2 + e];
        float4 va = cgA[kk];
        float4 vb = cgB[kk];
        acc[0] = fmaf(va.x, w, acc[0]);
        acc[1] = fmaf(va.y, w, acc[1]);
        acc[2] = fmaf(va.z, w, acc[2]);
        acc[3] = fmaf(va.w, w, acc[3]);
        acc[4] = fmaf(vb.x, w, acc[4]);
        acc[5] = fmaf(vb.y, w, acc[5]);
        acc[6] = fmaf(vb.z, w, acc[6]);
        acc[7] = fmaf(vb.w, w, acc[7]);
    }
    #pragma unroll
    for (int j = 0; j < PROJ_ROWS; j++) {
        int r = r0 + j;
        if (r < 272) {
            ubuf[r * E2 + e] = acc[j];
        } else if (r == 272) {
            ubuf[OFF_C + e] = acc[j] + (half == 0 ? b1[e] : 0.f);
        }
    }
}

// ---------------- main: R13-validated (R7 shape + SW-pipelined prefetch) ---
// Fill adds the two projection half-buffers (A+B) on the fly.
__global__ void __launch_bounds__(256, 2)
k_main(const float* __restrict__ W2, const float* __restrict__ b2,
       float* __restrict__ out) {
    extern __shared__ float sm[];
    float* s_tf = sm;                  // [16][SROW]: ut[t] + uf[f0+r]
    float* s_ux = sm + 16 * SROW;      // [16][SROW]
    float* s_c  = sm + 32 * SROW;      // [512] then w0[512], w1[512]

    int t   = blockIdx.x;
    int f0  = blockIdx.y * 16;
    int tid = threadIdx.x;

    // fill smem: 256 threads = 2 halves x 128 float4 columns
    {
        int half = tid >> 7;           // rows [8*half, 8*half+8)
        int e4   = tid & 127;
        float4 aA = ((const float4*)(g_uA + OFF_UT + t * E2))[e4];
        float4 aB = ((const float4*)(g_uB + OFF_UT + t * E2))[e4];
        float4 a = make_float4(aA.x + aB.x, aA.y + aB.y, aA.z + aB.z, aA.w + aB.w);
        #pragma unroll 4
        for (int r = half * 8; r < half * 8 + 8; r++) {
            float4 bA = ((const float4*)(g_uA + OFF_UF + (f0 + r) * E2))[e4];
            float4 bB = ((const float4*)(g_uB + OFF_UF + (f0 + r) * E2))[e4];
            ((float4*)(s_tf + r * SROW))[e4] =
                make_float4(a.x + bA.x + bB.x, a.y + bA.y + bB.y,
                            a.z + bA.z + bB.z, a.w + bA.w + bB.w);
            float4 xA = ((const float4*)(g_uA + r * E2))[e4];
            float4 xB = ((const float4*)(g_uB + r * E2))[e4];
            ((float4*)(s_ux + r * SROW))[e4] =
                make_float4(xA.x + xB.x, xA.y + xB.y, xA.z + xB.z, xA.w + xB.w);
        }
        for (int i = tid; i < E2; i += 256) {
            s_c[i]          = g_uA[OFF_C + i] + g_uB[OFF_C + i];
            s_c[E2 + i]     = W2[2 * i];        // w0
            s_c[2 * E2 + i] = W2[2 * i + 1];    // w1
        }
    }

    int eq   = tid >> 5;    // e-slice 0..7 (warp-uniform)
    int lane = tid & 31;
    int fg   = lane & 3;    // f = f0 + fg + 4*fi
    int bng  = lane >> 2;   // bn = bng + 8*bi

    // per-combo rinv (packed), from decomposed variance terms
    u64 rinv2[8];
    float qt = g_qt[t];
    #pragma unroll
    for (int fi = 0; fi < 4; fi++) {
        int f = f0 + fg + 4 * fi;
        float qtf = qt + g_qf[f] + 2.0f * g_dtf[t * 128 + f];
        #pragma unroll
        for (int bi = 0; bi < 2; bi++) {
            int bn = bng + 8 * bi;
            float var = (qtf + g_qx[bn]
                         + 2.0f * (g_dxt[bn * 128 + t] + g_dxf[bn * 128 + f]))
                        * (1.0f / 256.0f);
            rinv2[fi * 2 + bi] = pack2(rsqrtf(var + EPS));
        }
    }
    __syncthreads();

    // single base pointers; row strides become constant ull2 offsets
    const ulonglong2* ptf = (const ulonglong2*)(s_tf + fg * SROW) + eq * 16;   // +fi*516
    const ulonglong2* pux = (const ulonglong2*)(s_ux + bng * SROW) + eq * 16;  // +bi*1032
    const ulonglong2* pcv = (const ulonglong2*)s_c + eq * 16;                  // c, +128 w0, +256 w1

    u64 A0[8], A1[8];
    #pragma unroll
    for (int k = 0; k < 8; k++) { A0[k] = 0ull; A1[k] = 0ull; }

#define BODY(TF0_, TF1_, TF2_, TF3_, UX0_, UX1_, C_, V0_, V1_)                 \
    {                                                                          \
        ulonglong2 TFv[4] = {TF0_, TF1_, TF2_, TF3_};                          \
        _Pragma("unroll")                                                      \
        for (int fi = 0; fi < 4; fi++) {                                       \
            _Pragma("unroll")                                                  \
            for (int bi = 0; bi < 2; bi++) {                                   \
                ulonglong2 UXv = bi ? UX1_ : UX0_;                             \
                int k = fi * 2 + bi;                                           \
                u64 z0 = relu2(fma2(rinv2[k], add2(TFv[fi].x, UXv.x), C_.x));  \
                u64 z1 = relu2(fma2(rinv2[k], add2(TFv[fi].y, UXv.y), C_.y));  \
                A0[k] = fma2(z0, V0_.x, A0[k]);                                \
                A0[k] = fma2(z1, V0_.y, A0[k]);                                \
                A1[k] = fma2(z0, V1_.x, A1[k]);                                \
                A1[k] = fma2(z1, V1_.y, A1[k]);                                \
            }                                                                  \
        }                                                                      \
    }

    // software pipeline: prefetch i+1 before computing i
    ulonglong2 cTF0 = ptf[0], cTF1 = ptf[516], cTF2 = ptf[1032], cTF3 = ptf[1548];
    ulonglong2 cUX0 = pux[0], cUX1 = pux[1032];
    ulonglong2 cC   = pcv[0];

    #pragma unroll 3
    for (int i = 0; i < 15; i++) {
        ulonglong2 nTF0 = ptf[i + 1],        nTF1 = ptf[i + 1 + 516];
        ulonglong2 nTF2 = ptf[i + 1 + 1032], nTF3 = ptf[i + 1 + 1548];
        ulonglong2 nUX0 = pux[i + 1],        nUX1 = pux[i + 1 + 1032];
        ulonglong2 nC   = pcv[i + 1];
        ulonglong2 V0   = pcv[i + 128],      V1   = pcv[i + 256];

        BODY(cTF0, cTF1, cTF2, cTF3, cUX0, cUX1, cC, V0, V1);

        cTF0 = nTF0; cTF1 = nTF1; cTF2 = nTF2; cTF3 = nTF3;
        cUX0 = nUX0; cUX1 = nUX1; cC = nC;
    }
    {   // epilogue: i = 15
        ulonglong2 V0 = pcv[15 + 128], V1 = pcv[15 + 256];
        BODY(cTF0, cTF1, cTF2, cTF3, cUX0, cUX1, cC, V0, V1);
    }
#undef BODY

    // merge 8 e-slice partials via smem (stride 9 to break bank collisions)
    __syncthreads();                   // all smem-stream reads done
    float* mrg = sm;                   // [(kg*2+o)*9 + eq], 512*9 = 4608 floats
    #pragma unroll
    for (int k = 0; k < 8; k++) {
        int fi = k >> 1, bi = k & 1;
        int kg = (fg + 4 * fi) * 16 + (bng + 8 * bi);   // combo id 0..255
        mrg[(kg * 2 + 0) * 9 + eq] = sum2(A0[k]);
        mrg[(kg * 2 + 1) * 9 + eq] = sum2(A1[k]);
    }
    __syncthreads();

    // thread tid reduces combo kg = tid
    {
        float o0 = b2[0], o1 = b2[1];
        int base = tid * 18;
        #pragma unroll
        for (int q = 0; q < 8; q++) {
            o0 += mrg[base + q];
            o1 += mrg[base + 9 + q];
        }
        int f  = f0 + (tid >> 4);
        int bn = tid & 15;
        ((float2*)out)[(bn * NT + t) * NF + f] = make_float2(o0, o1);
    }
}

// ---------------- launch ----------------------------------------------------
extern "C" void kernel_launch(void* const* d_in, const int* in_sizes, int n_in,
                              void* d_out, int out_size) {
    const float* x     = (const float*)d_in[0];
    const float* t_emb = (const float*)d_in[1];
    const float* f_emb = (const float*)d_in[2];
    const float* ln_g  = (const float*)d_in[3];
    const float* ln_b  = (const float*)d_in[4];
    const float* W1    = (const float*)d_in[5];
    const float* b1    = (const float*)d_in[6];
    const float* W2    = (const float*)d_in[7];
    const float* b2    = (const float*)d_in[8];
    float* out = (float*)d_out;

    const int smem_bytes = (32 * SROW + 3 * E2) * (int)sizeof(float);  // 72192
    cudaFuncSetAttribute(k_main, cudaFuncAttributeMaxDynamicSharedMemorySize, smem_bytes);

    k_prep<<<DOTB_FIRST + DOTB_COUNT, 512>>>(x, t_emb, f_emb, ln_g, ln_b, W1, b1);
    dim3 grid(NT, 8);
    k_main<<<grid, 256, smem_bytes>>>(W2, b2, out);
}

// round 17
// speedup vs baseline: 1.0471x; 1.0471x over previous
#include <cuda_runtime.h>

#define DD   256
#define E2   512
#define NT   128
#define NF   128
#define NBN  16
#define SROW 516
#define EPS  1e-5f

typedef unsigned long long u64;

// ---------------- packed f32x2 helpers (Blackwell 2xFP32) ------------------
__device__ __forceinline__ u64 add2(u64 a, u64 b) {
    u64 d; asm("add.rn.f32x2 %0,%1,%2;" : "=l"(d) : "l"(a), "l"(b)); return d;
}
__device__ __forceinline__ u64 fma2(u64 a, u64 b, u64 c) {
    u64 d; asm("fma.rn.f32x2 %0,%1,%2,%3;" : "=l"(d) : "l"(a), "l"(b), "l"(c)); return d;
}
__device__ __forceinline__ u64 relu2(u64 a) {
    u64 d;
    asm("{\n\t.reg .f32 l,h;\n\tmov.b64 {l,h}, %1;\n\t"
        "max.f32 l, l, 0f00000000;\n\tmax.f32 h, h, 0f00000000;\n\t"
        "mov.b64 %0, {l,h};\n\t}" : "=l"(d) : "l"(a));
    return d;
}
__device__ __forceinline__ float sum2(u64 a) {
    float l, h; asm("mov.b64 {%0,%1}, %2;" : "=f"(l), "=f"(h) : "l"(a)); return l + h;
}
__device__ __forceinline__ u64 pack2(float v) {
    u64 d; asm("mov.b64 %0, {%1,%1};" : "=l"(d) : "f"(v)); return d;
}

// ---------------- scratch (device globals; no allocation allowed) ----------
__device__ float g_qx[NBN];
__device__ float g_qt[NT];
__device__ float g_qf[NF];
__device__ float g_dxt[NBN * NT];
__device__ float g_dxf[NBN * NF];
__device__ float g_dtf[NT * NF];
// projection output buffer: every slot plain-stored exactly once
// (e-half blocks with intra-block k-split merge) — no memset, no atomics.
#define U_TOTAL ((NBN + NT + NF) * E2 + E2)
__device__ __align__(16) float g_u[U_TOTAL];
#define G_UX (g_u)
#define G_UT (g_u + NBN * E2)
#define G_UF (g_u + (NBN + NT) * E2)
#define G_C  (g_u + (NBN + NT + NF) * E2)

// row id r in [0,272): 0..15 x, 16..143 t_emb, 144..271 f_emb
__device__ __forceinline__ const float* row_ptr(int r, const float* x,
                                                const float* t_emb,
                                                const float* f_emb) {
    if (r < 16)  return x + r * DD;
    if (r < 144) return t_emb + (r - 16) * DD;
    return f_emb + (r - 144) * DD;
}

// ---------------- P1 (single prep kernel) ----------------------------------
// blocks [0, 70):        W1 projection: 8 rows x e-half; 512 thr = 2 k-halves
//                        x 256 e (k-split latency, plain single stores)
// blocks [70, 86):       dtf GEMM tiles: 8 t-rows x 128 f per block
// blocks [86, 86+273):   dxt/dxf/q dots, 16 warps/block, one result per warp
#define PROJ_GROUPS 35
#define PROJ_BLOCKS (PROJ_GROUPS * 2)
#define PROJ_ROWS   8
#define DTF_BLOCKS  16
#define DOTB_FIRST  (PROJ_BLOCKS + DTF_BLOCKS)          // 86
#define DOTB_COUNT  273                                 // ceil(4368/16)
__global__ void __launch_bounds__(512)
k_prep(const float* __restrict__ x,
       const float* __restrict__ t_emb,
       const float* __restrict__ f_emb,
       const float* __restrict__ ln_g,
       const float* __restrict__ ln_b,
       const float* __restrict__ W1,
       const float* __restrict__ b1) {
    int tid  = threadIdx.x;
    int lane = tid & 31;
    int wid  = tid >> 5;

    if (blockIdx.x >= DOTB_FIRST) {
        // ------------- dxt / dxf / q segment (4368 warps) -------------
        int w = (blockIdx.x - DOTB_FIRST) * 16 + wid;
        if (w >= 4368) return;
        int ra, rb;
        float* dst;
        if (w < 2048) {                        // dxt: x . t
            ra = w >> 7; rb = 16 + (w & 127); dst = g_dxt + w;
        } else if (w < 4096) {                 // dxf: x . f
            int w2 = w - 2048;
            ra = w2 >> 7; rb = 144 + (w2 & 127); dst = g_dxf + w2;
        } else {                               // self q
            int r = w - 4096;                  // 0..271
            const float4* a4 = (const float4*)row_ptr(r, x, t_emb, f_emb);
            float4 a0 = a4[lane * 2], a1 = a4[lane * 2 + 1];
            float sa  = a0.x + a0.y + a0.z + a0.w + a1.x + a1.y + a1.z + a1.w;
            float saa = a0.x * a0.x + a0.y * a0.y + a0.z * a0.z + a0.w * a0.w
                      + a1.x * a1.x + a1.y * a1.y + a1.z * a1.z + a1.w * a1.w;
            #pragma unroll
            for (int o = 16; o; o >>= 1) {
                sa  += __shfl_xor_sync(0xffffffffu, sa, o);
                saa += __shfl_xor_sync(0xffffffffu, saa, o);
            }
            if (lane == 0) {
                float q = saa - sa * sa * (1.0f / DD);
                if (r < 16)       g_qx[r] = q;
                else if (r < 144) g_qt[r - 16] = q;
                else              g_qf[r - 144] = q;
            }
            return;
        }
        const float4* a4 = (const float4*)row_ptr(ra, x, t_emb, f_emb);
        const float4* b4 = (const float4*)row_ptr(rb, x, t_emb, f_emb);
        float4 a0 = a4[lane * 2], a1 = a4[lane * 2 + 1];
        float4 b0 = b4[lane * 2], b1v = b4[lane * 2 + 1];
        float sa  = a0.x + a0.y + a0.z + a0.w + a1.x + a1.y + a1.z + a1.w;
        float sb  = b0.x + b0.y + b0.z + b0.w + b1v.x + b1v.y + b1v.z + b1v.w;
        float sab = a0.x * b0.x + a0.y * b0.y + a0.z * b0.z + a0.w * b0.w
                  + a1.x * b1v.x + a1.y * b1v.y + a1.z * b1v.z + a1.w * b1v.w;
        #pragma unroll
        for (int o = 16; o; o >>= 1) {
            sa  += __shfl_xor_sync(0xffffffffu, sa, o);
            sb  += __shfl_xor_sync(0xffffffffu, sb, o);
            sab += __shfl_xor_sync(0xffffffffu, sab, o);
        }
        if (lane == 0) *dst = sab - sa * sb * (1.0f / DD);
        return;
    }

    if (blockIdx.x >= PROJ_BLOCKS) {
        // ------------- dtf GEMM tile: 8 t-rows x all 128 f -------------
        __shared__ float st[8][DD];
        __shared__ float ssum[8];
        int t0 = (blockIdx.x - PROJ_BLOCKS) * 8;

        for (int i = tid; i < 8 * DD; i += 512)
            st[i >> 8][i & 255] = t_emb[t0 * DD + i];
        __syncthreads();

        if (wid < 8) {   // row sums
            const float4* r4 = (const float4*)st[wid];
            float4 v0 = r4[lane * 2], v1 = r4[lane * 2 + 1];
            float s = v0.x + v0.y + v0.z + v0.w + v1.x + v1.y + v1.z + v1.w;
            #pragma unroll
            for (int o = 16; o; o >>= 1) s += __shfl_xor_sync(0xffffffffu, s, o);
            if (lane == 0) ssum[wid] = s;
        }
        __syncthreads();

        // warp wid handles f rows [wid*8, wid*8+8)
        for (int fi = 0; fi < 8; fi++) {
            int f = wid * 8 + fi;
            const float4* f4 = (const float4*)(f_emb + f * DD);
            float4 a0 = f4[lane * 2], a1 = f4[lane * 2 + 1];
            float sf = a0.x + a0.y + a0.z + a0.w + a1.x + a1.y + a1.z + a1.w;
            float acc[8];
            #pragma unroll
            for (int tl = 0; tl < 8; tl++) {
                const float4* s4 = (const float4*)st[tl];
                float4 b0 = s4[lane * 2], b1v = s4[lane * 2 + 1];
                acc[tl] = a0.x * b0.x + a0.y * b0.y + a0.z * b0.z + a0.w * b0.w
                        + a1.x * b1v.x + a1.y * b1v.y + a1.z * b1v.z + a1.w * b1v.w;
            }
            #pragma unroll
            for (int o = 16; o; o >>= 1) {
                sf += __shfl_xor_sync(0xffffffffu, sf, o);
                #pragma unroll
                for (int tl = 0; tl < 8; tl++)
                    acc[tl] += __shfl_xor_sync(0xffffffffu, acc[tl], o);
            }
            if (lane == 0) {
                #pragma unroll
                for (int tl = 0; tl < 8; tl++)
                    g_dtf[(t0 + tl) * NF + f] = acc[tl] - ssum[tl] * sf * (1.0f / DD);
            }
        }
        return;
    }

    // --------- projection: 8 rows x e-half; 2 k-halves merged in-block -----
    __shared__ float  s_mu[PROJ_ROWS];
    __shared__ float4 cgA[DD];            // [k] rows r0..r0+3, k = 0..255
    __shared__ float4 cgB[DD];            // [k] rows r0+4..r0+7
    __shared__ float  pm[PROJ_ROWS][256]; // k-half-1 partials
    int eh = blockIdx.x & 1;              // e-half
    int rg = blockIdx.x >> 1;
    int r0 = rg * PROJ_ROWS;

    // warps 0..7: full-row means (row 272 = ln_b, uncentered)
    if (wid < PROJ_ROWS) {
        int r = r0 + wid;
        float mu = 0.f;
        if (r < 272) {
            const float4* a4 = (const float4*)row_ptr(r, x, t_emb, f_emb);
            float4 a0 = a4[lane * 2], a1 = a4[lane * 2 + 1];
            float s = a0.x + a0.y + a0.z + a0.w + a1.x + a1.y + a1.z + a1.w;
            #pragma unroll
            for (int o = 16; o; o >>= 1) s += __shfl_xor_sync(0xffffffffu, s, o);
            mu = s * (1.0f / DD);
        }
        if (lane == 0) s_mu[wid] = mu;
    }
    __syncthreads();

    // threads 0..255 build the full-k centered tile (k = tid)
    if (tid < DD) {
        int k = tid;
        float g = ln_g[k];
        float v[PROJ_ROWS];
        #pragma unroll
        for (int j = 0; j < PROJ_ROWS; j++) {
            int r = r0 + j;
            float c;
            if (r < 272)       c = (row_ptr(r, x, t_emb, f_emb)[k] - s_mu[j]) * g;
            else if (r == 272) c = ln_b[k];
            else               c = 0.f;
            v[j] = c;
        }
        cgA[k] = make_float4(v[0], v[1], v[2], v[3]);
        cgB[k] = make_float4(v[4], v[5], v[6], v[7]);
    }
    __syncthreads();

    int kh = tid >> 8;            // k-half 0/1
    int el = tid & 255;           // e within half
    int e  = eh * 256 + el;
    int kb = kh * 128;

    float acc[PROJ_ROWS];
    #pragma unroll
    for (int j = 0; j < PROJ_ROWS; j++) acc[j] = 0.f;
    #pragma unroll 16
    for (int kk = 0; kk < 128; kk++) {
        int k = kb + kk;
        float w = W1[k * E2 + e];
        float4 va = cgA[k];
        float4 vb = cgB[k];
        acc[0] = fmaf(va.x, w, acc[0]);
        acc[1] = fmaf(va.y, w, acc[1]);
        acc[2] = fmaf(va.z, w, acc[2]);
        acc[3] = fmaf(va.w, w, acc[3]);
        acc[4] = fmaf(vb.x, w, acc[4]);
        acc[5] = fmaf(vb.y, w, acc[5]);
        acc[6] = fmaf(vb.z, w, acc[6]);
        acc[7] = fmaf(vb.w, w, acc[7]);
    }

    if (kh == 1) {
        #pragma unroll
        for (int j = 0; j < PROJ_ROWS; j++) pm[j][el] = acc[j];
    }
    __syncthreads();
    if (kh == 0) {
        #pragma unroll
        for (int j = 0; j < PROJ_ROWS; j++) {
            float s = acc[j] + pm[j][el];
            int r = r0 + j;
            if (r < 272)       g_u[r * E2 + e] = s;
            else if (r == 272) G_C[e] = s + b1[e];
        }
    }
}

// ---------------- main: R13/R15-validated (R7 shape + SW-pipelined prefetch)
__global__ void __launch_bounds__(256, 2)
k_main(const float* __restrict__ W2, const float* __restrict__ b2,
       float* __restrict__ out) {
    extern __shared__ float sm[];
    float* s_tf = sm;                  // [16][SROW]: ut[t] + uf[f0+r]
    float* s_ux = sm + 16 * SROW;      // [16][SROW]
    float* s_c  = sm + 32 * SROW;      // [512] then w0[512], w1[512]

    int t   = blockIdx.x;
    int f0  = blockIdx.y * 16;
    int tid = threadIdx.x;

    // fill smem: 256 threads = 2 halves x 128 float4 columns
    {
        int half = tid >> 7;           // rows [8*half, 8*half+8)
        int e4   = tid & 127;
        const float4* ut4 = (const float4*)(G_UT + t * E2);
        float4 a = ut4[e4];
        #pragma unroll 4
        for (int r = half * 8; r < half * 8 + 8; r++) {
            float4 b = ((const float4*)(G_UF + (f0 + r) * E2))[e4];
            ((float4*)(s_tf + r * SROW))[e4] =
                make_float4(a.x + b.x, a.y + b.y, a.z + b.z, a.w + b.w);
            ((float4*)(s_ux + r * SROW))[e4] = ((const float4*)(G_UX + r * E2))[e4];
        }
        for (int i = tid; i < E2; i += 256) {
            s_c[i]          = G_C[i];
            s_c[E2 + i]     = W2[2 * i];        // w0
            s_c[2 * E2 + i] = W2[2 * i + 1];    // w1
        }
    }

    int eq   = tid >> 5;    // e-slice 0..7 (warp-uniform)
    int lane = tid & 31;
    int fg   = lane & 3;    // f = f0 + fg + 4*fi
    int bng  = lane >> 2;   // bn = bng + 8*bi

    // per-combo rinv (packed), from decomposed variance terms
    u64 rinv2[8];
    float qt = g_qt[t];
    #pragma unroll
    for (int fi = 0; fi < 4; fi++) {
        int f = f0 + fg + 4 * fi;
        float qtf = qt + g_qf[f] + 2.0f * g_dtf[t * 128 + f];
        #pragma unroll
        for (int bi = 0; bi < 2; bi++) {
            int bn = bng + 8 * bi;
            float var = (qtf + g_qx[bn]
                         + 2.0f * (g_dxt[bn * 128 + t] + g_dxf[bn * 128 + f]))
                        * (1.0f / 256.0f);
            rinv2[fi * 2 + bi] = pack2(rsqrtf(var + EPS));
        }
    }
    __syncthreads();

    // single base pointers; row strides become constant ull2 offsets
    const ulonglong2* ptf = (const ulonglong2*)(s_tf + fg * SROW) + eq * 16;   // +fi*516
    const ulonglong2* pux = (const ulonglong2*)(s_ux + bng * SROW) + eq * 16;  // +bi*1032
    const ulonglong2* pcv = (const ulonglong2*)s_c + eq * 16;                  // c, +128 w0, +256 w1

    u64 A0[8], A1[8];
    #pragma unroll
    for (int k = 0; k < 8; k++) { A0[k] = 0ull; A1[k] = 0ull; }

#define BODY(TF0_, TF1_, TF2_, TF3_, UX0_, UX1_, C_, V0_, V1_)                 \
    {                                                                          \
        ulonglong2 TFv[4] = {TF0_, TF1_, TF2_, TF3_};                          \
        _Pragma("unroll")                                                      \
        for (int fi = 0; fi < 4; fi++) {                                       \
            _Pragma("unroll")                                                  \
            for (int bi = 0; bi < 2; bi++) {                                   \
                ulonglong2 UXv = bi ? UX1_ : UX0_;                             \
                int k = fi * 2 + bi;                                           \
                u64 z0 = relu2(fma2(rinv2[k], add2(TFv[fi].x, UXv.x), C_.x));  \
                u64 z1 = relu2(fma2(rinv2[k], add2(TFv[fi].y, UXv.y), C_.y));  \
                A0[k] = fma2(z0, V0_.x, A0[k]);                                \
                A0[k] = fma2(z1, V0_.y, A0[k]);                                \
                A1[k] = fma2(z0, V1_.x, A1[k]);                                \
                A1[k] = fma2(z1, V1_.y, A1[k]);                                \
            }                                                                  \
        }                                                                      \
    }

    // software pipeline: prefetch i+1 before computing i
    ulonglong2 cTF0 = ptf[0], cTF1 = ptf[516], cTF2 = ptf[1032], cTF3 = ptf[1548];
    ulonglong2 cUX0 = pux[0], cUX1 = pux[1032];
    ulonglong2 cC   = pcv[0];

    #pragma unroll 3
    for (int i = 0; i < 15; i++) {
        ulonglong2 nTF0 = ptf[i + 1],        nTF1 = ptf[i + 1 + 516];
        ulonglong2 nTF2 = ptf[i + 1 + 1032], nTF3 = ptf[i + 1 + 1548];
        ulonglong2 nUX0 = pux[i + 1],        nUX1 = pux[i + 1 + 1032];
        ulonglong2 nC   = pcv[i + 1];
        ulonglong2 V0   = pcv[i + 128],      V1   = pcv[i + 256];

        BODY(cTF0, cTF1, cTF2, cTF3, cUX0, cUX1, cC, V0, V1);

        cTF0 = nTF0; cTF1 = nTF1; cTF2 = nTF2; cTF3 = nTF3;
        cUX0 = nUX0; cUX1 = nUX1; cC = nC;
    }
    {   // epilogue: i = 15
        ulonglong2 V0 = pcv[15 + 128], V1 = pcv[15 + 256];
        BODY(cTF0, cTF1, cTF2, cTF3, cUX0, cUX1, cC, V0, V1);
    }
#undef BODY

    // merge 8 e-slice partials via smem (stride 9 to break bank collisions)
    __syncthreads();                   // all smem-stream reads done
    float* mrg = sm;                   // [(kg*2+o)*9 + eq], 512*9 = 4608 floats
    #pragma unroll
    for (int k = 0; k < 8; k++) {
        int fi = k >> 1, bi = k & 1;
        int kg = (fg + 4 * fi) * 16 + (bng + 8 * bi);   // combo id 0..255
        mrg[(kg * 2 + 0) * 9 + eq] = sum2(A0[k]);
        mrg[(kg * 2 + 1) * 9 + eq] = sum2(A1[k]);
    }
    __syncthreads();

    // thread tid reduces combo kg = tid
    {
        float o0 = b2[0], o1 = b2[1];
        int base = tid * 18;
        #pragma unroll
        for (int q = 0; q < 8; q++) {
            o0 += mrg[base + q];
            o1 += mrg[base + 9 + q];
        }
        int f  = f0 + (tid >> 4);
        int bn = tid & 15;
        ((float2*)out)[(bn * NT + t) * NF + f] = make_float2(o0, o1);
    }
}

// ---------------- launch ----------------------------------------------------
extern "C" void kernel_launch(void* const* d_in, const int* in_sizes, int n_in,
                              void* d_out, int out_size) {
    const float* x     = (const float*)d_in[0];
    const float* t_emb = (const float*)d_in[1];
    const float* f_emb = (const float*)d_in[2];
    const float* ln_g  = (const float*)d_in[3];
    const float* ln_b  = (const float*)d_in[4];
    const float* W1    = (const float*)d_in[5];
    const float* b1    = (const float*)d_in[6];
    const float* W2    = (const float*)d_in[7];
    const float* b2    = (const float*)d_in[8];
    float* out = (float*)d_out;

    const int smem_bytes = (32 * SROW + 3 * E2) * (int)sizeof(float);  // 72192
    cudaFuncSetAttribute(k_main, cudaFuncAttributeMaxDynamicSharedMemorySize, smem_bytes);

    k_prep<<<DOTB_FIRST + DOTB_COUNT, 512>>>(x, t_emb, f_emb, ln_g, ln_b, W1, b1);
    dim3 grid(NT, 8);
    k_main<<<grid, 256, smem_bytes>>>(W2, b2, out);
}